// round 16
// baseline (speedup 1.0000x reference)
#include <cuda_runtime.h>
#include <cuda_fp16.h>
#include <cstdint>

#define M_NODES 50000
#define K_NBR   32
#define DCH     256
#define NPN     8            // nodes per gather block (50000 = 6250 * 8)

__device__ __half g_hh[M_NODES * DCH];   // h stored fp16
__device__ __half g_wh[DCH * DCH];       // W in fp16

// ===================== W -> fp16 (tiny) ======================================
__global__ void __launch_bounds__(256) convert_w(const float* __restrict__ w) {
    size_t i4 = (size_t)blockIdx.x * 256 + threadIdx.x;
    if (i4 * 4 >= (size_t)DCH * DCH) return;
    float4 f = *reinterpret_cast<const float4*>(w + i4 * 4);
    __half2 p01 = __floats2half2_rn(f.x, f.y);
    __half2 p23 = __floats2half2_rn(f.z, f.w);
    reinterpret_cast<uint2*>(g_wh)[i4] =
        make_uint2(*reinterpret_cast<uint32_t*>(&p01), *reinterpret_cast<uint32_t*>(&p23));
}

// ===================== mma.sync fp16 GEMM, BM=128 BN=256, K=256 ==============
// 512 threads, 16 warps (4m x 4n), warp tile 32x64. B fetched via cp.async
// (fp16 already, no conversion); A (x) converted fp32->fp16 in registers.
#define AS_LD    40                          // halves/row (32 data + 8 pad) = 80B
#define A_BUF_B  (128 * AS_LD * 2)           // 10240 B per A buffer
#define B_BUF_B  (256 * AS_LD * 2)           // 20480 B per B buffer
#define GEMM_SMEM (2 * (A_BUF_B + B_BUF_B))  // 61440 B

__device__ __forceinline__ uint32_t smem_u32(const void* p) {
    uint32_t a;
    asm("{ .reg .u64 t; cvta.to.shared.u64 t, %1; cvt.u32.u64 %0, t; }" : "=r"(a) : "l"(p));
    return a;
}
__device__ __forceinline__ void cp16(uint32_t s, const void* g) {
    asm volatile("cp.async.cg.shared.global [%0], [%1], 16;" :: "r"(s), "l"(g));
}
__device__ __forceinline__ void ldsm_x4(uint32_t* r, uint32_t addr) {
    asm volatile("ldmatrix.sync.aligned.m8n8.x4.shared.b16 {%0,%1,%2,%3}, [%4];"
                 : "=r"(r[0]), "=r"(r[1]), "=r"(r[2]), "=r"(r[3]) : "r"(addr));
}
__device__ __forceinline__ void ldsm_x2(uint32_t* r, uint32_t addr) {
    asm volatile("ldmatrix.sync.aligned.m8n8.x2.shared.b16 {%0,%1}, [%2];"
                 : "=r"(r[0]), "=r"(r[1]) : "r"(addr));
}
__device__ __forceinline__ void mma_f16(float* d, const uint32_t* a, const uint32_t* b) {
    asm volatile(
        "mma.sync.aligned.m16n8k16.row.col.f32.f16.f16.f32 "
        "{%0,%1,%2,%3}, {%4,%5,%6,%7}, {%8,%9}, {%0,%1,%2,%3};"
        : "+f"(d[0]), "+f"(d[1]), "+f"(d[2]), "+f"(d[3])
        : "r"(a[0]), "r"(a[1]), "r"(a[2]), "r"(a[3]), "r"(b[0]), "r"(b[1]));
}

__global__ void __launch_bounds__(512) gemm_mma(const float* __restrict__ x) {
    extern __shared__ __align__(16) char smem[];
    __half* As = reinterpret_cast<__half*>(smem);                       // 2 bufs
    __half* Bs = reinterpret_cast<__half*>(smem + 2 * A_BUF_B);         // 2 bufs

    const int tid  = threadIdx.x;
    const int bm   = blockIdx.x * 128;
    const int warp = tid >> 5, lane = tid & 31;
    const int mw   = warp >> 2, nw = warp & 3;      // 4m x 4n warps

    float acc[2][8][4];
#pragma unroll
    for (int mt = 0; mt < 2; mt++)
#pragma unroll
        for (int nt = 0; nt < 8; nt++)
#pragma unroll
            for (int q = 0; q < 4; q++) acc[mt][nt][q] = 0.0f;

    float4 ar[2];    // A: 1024 float4 chunks, 2/thread

    auto ldA = [&](int kt) {
        const int kk = kt * 32;
#pragma unroll
        for (int l = 0; l < 2; l++) {
            int t = tid + l * 512, r = t >> 3, j = t & 7;
            int row = bm + r;
            float4 v = make_float4(0.f, 0.f, 0.f, 0.f);
            if (row < M_NODES)
                v = *reinterpret_cast<const float4*>(x + (size_t)row * DCH + kk + j * 4);
            ar[l] = v;
        }
    };

    auto cpB = [&](int kt, int buf) {
        const int kk = kt * 32;
        uint32_t b_dst = smem_u32(Bs + buf * (B_BUF_B / 2));
#pragma unroll
        for (int l = 0; l < 2; l++) {
            int t = tid + l * 512, r = t >> 2, j = t & 3;   // 4 x 16B per row
            cp16(b_dst + (uint32_t)(r * 80 + j * 16),
                 g_wh + (size_t)r * DCH + kk + j * 8);
        }
        asm volatile("cp.async.commit_group;" ::: "memory");
    };

    auto stsA = [&](int buf) {
        __half* a_dst = As + buf * (A_BUF_B / 2);
#pragma unroll
        for (int l = 0; l < 2; l++) {
            int t = tid + l * 512, r = t >> 3, j = t & 7;
            float4 v = ar[l];
            __half2 p0 = __floats2half2_rn(v.x, v.y);
            __half2 p1 = __floats2half2_rn(v.z, v.w);
            *reinterpret_cast<uint2*>(&a_dst[r * AS_LD + j * 4]) =
                make_uint2(*reinterpret_cast<uint32_t*>(&p0), *reinterpret_cast<uint32_t*>(&p1));
        }
    };

    auto compute = [&](int buf) {
        const uint32_t as_b = smem_u32(As + buf * (A_BUF_B / 2));
        const uint32_t bs_b = smem_u32(Bs + buf * (B_BUF_B / 2));
#pragma unroll
        for (int ks = 0; ks < 2; ks++) {
            const int k0 = ks * 16;
            uint32_t afrag[2][4];
#pragma unroll
            for (int mt = 0; mt < 2; mt++)
                ldsm_x4(afrag[mt], as_b + 2u * ((mw * 32 + mt * 16 + (lane & 15)) * AS_LD +
                                                (lane >> 4) * 8 + k0));
            uint32_t bfrag[8][2];
#pragma unroll
            for (int nt = 0; nt < 8; nt++)
                ldsm_x2(bfrag[nt], bs_b + 2u * ((nw * 64 + nt * 8 + (lane & 7)) * AS_LD +
                                                ((lane >> 3) & 1) * 8 + k0));
#pragma unroll
            for (int mt = 0; mt < 2; mt++)
#pragma unroll
                for (int nt = 0; nt < 8; nt++)
                    mma_f16(acc[mt][nt], afrag[mt], bfrag[nt]);
        }
    };

    // prologue: A(0) via registers, B(0) via cp.async
    ldA(0);
    cpB(0, 0);
    stsA(0);

#pragma unroll 1
    for (int kt = 0; kt < 8; kt++) {
        const int buf = kt & 1;
        // B(kt) was committed last iteration (or prologue); one group in flight
        asm volatile("cp.async.wait_group 0;" ::: "memory");
        __syncthreads();                         // B(kt)+A(kt) visible; buf^1 free
        if (kt < 7) {
            ldA(kt + 1);                         // LDG latency hidden by compute
            cpB(kt + 1, buf ^ 1);                // async, overlaps compute+stsA
        }
        compute(buf);
        if (kt < 7) stsA(buf ^ 1);
    }

    // epilogue: acc -> g_hh (fp16 packed pairs)
#pragma unroll
    for (int mt = 0; mt < 2; mt++) {
        const int m0 = bm + mw * 32 + mt * 16 + (lane >> 2);
#pragma unroll
        for (int nt = 0; nt < 8; nt++) {
            const int n = nw * 64 + nt * 8 + (lane & 3) * 2;
            __half2 p01 = __floats2half2_rn(acc[mt][nt][0], acc[mt][nt][1]);
            __half2 p23 = __floats2half2_rn(acc[mt][nt][2], acc[mt][nt][3]);
            if (m0 < M_NODES)
                *reinterpret_cast<__half2*>(&g_hh[(size_t)m0 * DCH + n]) = p01;
            if (m0 + 8 < M_NODES)
                *reinterpret_cast<__half2*>(&g_hh[(size_t)(m0 + 8) * DCH + n]) = p23;
        }
    }
}

// ===================== gather: register ping-pong pipeline (R14 proven) ======
#define CE2(arr, a, b) { __half2 _mn = __hmin2(arr[a], arr[b]); \
                         __half2 _mx = __hmax2(arr[a], arr[b]); \
                         arr[a] = _mn; arr[b] = _mx; }

#define OEMS16(arr, o) \
    CE2(arr,o+0,o+1)  CE2(arr,o+2,o+3)   CE2(arr,o+4,o+5)   CE2(arr,o+6,o+7) \
    CE2(arr,o+8,o+9)  CE2(arr,o+10,o+11) CE2(arr,o+12,o+13) CE2(arr,o+14,o+15) \
    CE2(arr,o+0,o+2)  CE2(arr,o+1,o+3)   CE2(arr,o+4,o+6)   CE2(arr,o+5,o+7) \
    CE2(arr,o+8,o+10) CE2(arr,o+9,o+11)  CE2(arr,o+12,o+14) CE2(arr,o+13,o+15) \
    CE2(arr,o+1,o+2)  CE2(arr,o+5,o+6)   CE2(arr,o+9,o+10)  CE2(arr,o+13,o+14) \
    CE2(arr,o+0,o+4)  CE2(arr,o+1,o+5)   CE2(arr,o+2,o+6)   CE2(arr,o+3,o+7) \
    CE2(arr,o+8,o+12) CE2(arr,o+9,o+13)  CE2(arr,o+10,o+14) CE2(arr,o+11,o+15) \
    CE2(arr,o+2,o+4)  CE2(arr,o+3,o+5)   CE2(arr,o+10,o+12) CE2(arr,o+11,o+13) \
    CE2(arr,o+1,o+2)  CE2(arr,o+3,o+4)   CE2(arr,o+5,o+6) \
    CE2(arr,o+9,o+10) CE2(arr,o+11,o+12) CE2(arr,o+13,o+14) \
    CE2(arr,o+0,o+8)  CE2(arr,o+1,o+9)   CE2(arr,o+2,o+10)  CE2(arr,o+3,o+11) \
    CE2(arr,o+4,o+12) CE2(arr,o+5,o+13)  CE2(arr,o+6,o+14)  CE2(arr,o+7,o+15) \
    CE2(arr,o+4,o+8)  CE2(arr,o+5,o+9)   CE2(arr,o+6,o+10)  CE2(arr,o+7,o+11) \
    CE2(arr,o+2,o+4)  CE2(arr,o+3,o+5)   CE2(arr,o+6,o+8) \
    CE2(arr,o+7,o+9)  CE2(arr,o+10,o+12) CE2(arr,o+11,o+13) \
    CE2(arr,o+1,o+2)  CE2(arr,o+3,o+4)   CE2(arr,o+5,o+6)   CE2(arr,o+7,o+8) \
    CE2(arr,o+9,o+10) CE2(arr,o+11,o+12) CE2(arr,o+13,o+14)

#define SELECT32(arr) \
    OEMS16(arr, 0) \
    OEMS16(arr, 16) \
    _Pragma("unroll") \
    for (int i = 0; i < 16; i++) { \
        __half2 _a = arr[i], _b = arr[31 - i]; \
        arr[i]      = __hmin2(_a, _b); \
        arr[31 - i] = __hmax2(_a, _b); \
    } \
    _Pragma("unroll") \
    for (int j = 8; j >= 2; j >>= 1) \
        _Pragma("unroll") \
        for (int i = 0; i < j; i++) \
            arr[i] = __hmax2(arr[i], arr[i + j]); \
    _Pragma("unroll") \
    for (int j = 8; j >= 2; j >>= 1) \
        _Pragma("unroll") \
        for (int i = 0; i < j; i++) \
            arr[16 + i] = __hmin2(arr[16 + i], arr[16 + i + j]);

#define EMIT(arr, nodeidx) { \
    float2 _f0 = __half22float2(arr[0]); \
    float2 _f1 = __half22float2(arr[1]); \
    float2 _f2 = __half22float2(arr[16]); \
    float2 _f3 = __half22float2(arr[17]); \
    float2 _r  = make_float2((_f0.x + _f1.x + _f2.x + _f3.x) * 0.25f, \
                             (_f0.y + _f1.y + _f2.y + _f3.y) * 0.25f); \
    *reinterpret_cast<float2*>(&out[(size_t)(nodeidx) * DCH + 2 * tid]) = _r; }

#define LOADV(arr, j) { \
    _Pragma("unroll") \
    for (int k = 0; k < K_NBR; k++) \
        arr[k] = *reinterpret_cast<const __half2*>(&g_hh[sn[j][k] + 2 * tid]); }

__global__ void __launch_bounds__(128) gather_trim(
    const void* __restrict__ nbrs_raw,
    float* __restrict__ out)
{
    __shared__ int sn[NPN][K_NBR];

    const int tid   = threadIdx.x;
    const int node0 = blockIdx.x * NPN;

    {
        const int* w = reinterpret_cast<const int*>(nbrs_raw);
        unsigned m = __ballot_sync(0xffffffffu, w[2 * (tid & 31) + 1] == 0);
        bool is64 = (m == 0xffffffffu);
#pragma unroll
        for (int i = tid; i < NPN * K_NBR; i += 128) {
            int nl = i >> 5, k = i & 31;
            long long nd = (long long)node0 + nl;
            long long idx = is64
                ? reinterpret_cast<const long long*>(nbrs_raw)[nd * K_NBR + k]
                : (long long)reinterpret_cast<const int*>(nbrs_raw)[nd * K_NBR + k];
            sn[nl][k] = (int)idx * DCH;
        }
    }
    __syncthreads();

    __half2 A[K_NBR], B[K_NBR];

    LOADV(A, 0)
#pragma unroll
    for (int j = 0; j < NPN; j += 2) {
        if (j + 1 < NPN) LOADV(B, j + 1)
        SELECT32(A)
        EMIT(A, node0 + j)
        if (j + 2 < NPN) LOADV(A, j + 2)
        if (j + 1 < NPN) {
            SELECT32(B)
            EMIT(B, node0 + j + 1)
        }
    }
}

// ===================== launch ===============================================
extern "C" void kernel_launch(void* const* d_in, const int* in_sizes, int n_in,
                              void* d_out, int out_size)
{
    const float* x    = nullptr;
    const void*  nbrs = nullptr;
    const float* W    = nullptr;

    for (int i = 0; i < n_in; i++) {
        if      (in_sizes[i] == M_NODES * DCH)   x    = (const float*)d_in[i];
        else if (in_sizes[i] == M_NODES * K_NBR) nbrs = d_in[i];
        else if (in_sizes[i] == DCH * DCH)       W    = (const float*)d_in[i];
    }
    if (!x)    x    = (const float*)d_in[0];
    if (!nbrs) nbrs = d_in[1];
    if (!W)    W    = (const float*)d_in[2];

    cudaFuncSetAttribute(gemm_mma, cudaFuncAttributeMaxDynamicSharedMemorySize, GEMM_SMEM);

    convert_w<<<(DCH * DCH / 4 + 255) / 256, 256>>>(W);

    gemm_mma<<<(M_NODES + 127) / 128, 512, GEMM_SMEM>>>(x);

    gather_trim<<<M_NODES / NPN, 128>>>(nbrs, (float*)d_out);
}

// round 17
// speedup vs baseline: 1.0302x; 1.0302x over previous
#include <cuda_runtime.h>
#include <cuda_fp16.h>
#include <cstdint>

#define M_NODES 50000
#define K_NBR   32
#define DCH     256
#define NPN     8            // nodes per gather block (50000 = 6250 * 8)

__device__ __half g_hh[M_NODES * DCH];   // h stored fp16

// ===================== mma.sync fp16 GEMM, BM=128 BN=256, K=256 ==============
// 512 threads, 16 warps (4m x 4n), warp tile 32x64 (proven addressing).
// BOTH x and W read fp32 and converted fp32->fp16 in registers (no separate
// convert kernel); double-buffered BK=32.
#define AS_LD    40                          // halves/row (32 data + 8 pad) = 80B
#define A_BUF_B  (128 * AS_LD * 2)           // 10240 B per A buffer
#define B_BUF_B  (256 * AS_LD * 2)           // 20480 B per B buffer
#define GEMM_SMEM (2 * (A_BUF_B + B_BUF_B))  // 61440 B

__device__ __forceinline__ uint32_t smem_u32(const void* p) {
    uint32_t a;
    asm("{ .reg .u64 t; cvta.to.shared.u64 t, %1; cvt.u32.u64 %0, t; }" : "=r"(a) : "l"(p));
    return a;
}
__device__ __forceinline__ void ldsm_x4(uint32_t* r, uint32_t addr) {
    asm volatile("ldmatrix.sync.aligned.m8n8.x4.shared.b16 {%0,%1,%2,%3}, [%4];"
                 : "=r"(r[0]), "=r"(r[1]), "=r"(r[2]), "=r"(r[3]) : "r"(addr));
}
__device__ __forceinline__ void ldsm_x2(uint32_t* r, uint32_t addr) {
    asm volatile("ldmatrix.sync.aligned.m8n8.x2.shared.b16 {%0,%1}, [%2];"
                 : "=r"(r[0]), "=r"(r[1]) : "r"(addr));
}
__device__ __forceinline__ void mma_f16(float* d, const uint32_t* a, const uint32_t* b) {
    asm volatile(
        "mma.sync.aligned.m16n8k16.row.col.f32.f16.f16.f32 "
        "{%0,%1,%2,%3}, {%4,%5,%6,%7}, {%8,%9}, {%0,%1,%2,%3};"
        : "+f"(d[0]), "+f"(d[1]), "+f"(d[2]), "+f"(d[3])
        : "r"(a[0]), "r"(a[1]), "r"(a[2]), "r"(a[3]), "r"(b[0]), "r"(b[1]));
}

__global__ void __launch_bounds__(512) gemm_mma(const float* __restrict__ x,
                                                const float* __restrict__ w) {
    extern __shared__ __align__(16) char smem[];
    __half* As = reinterpret_cast<__half*>(smem);                       // 2 bufs
    __half* Bs = reinterpret_cast<__half*>(smem + 2 * A_BUF_B);         // 2 bufs

    const int tid  = threadIdx.x;
    const int bm   = blockIdx.x * 128;
    const int warp = tid >> 5, lane = tid & 31;
    const int mw   = warp >> 2, nw = warp & 3;      // 4m x 4n warps

    float acc[2][8][4];
#pragma unroll
    for (int mt = 0; mt < 2; mt++)
#pragma unroll
        for (int nt = 0; nt < 8; nt++)
#pragma unroll
            for (int q = 0; q < 4; q++) acc[mt][nt][q] = 0.0f;

    float4 ar[2];    // A: 1024 float4 chunks, 2/thread
    float4 br[4];    // B: 2048 float4 chunks, 4/thread (fp32 W)

    auto load_g = [&](int kt) {
        const int kk = kt * 32;
#pragma unroll
        for (int l = 0; l < 2; l++) {
            int t = tid + l * 512, r = t >> 3, j = t & 7;   // 8 float4 per row
            int row = bm + r;
            float4 v = make_float4(0.f, 0.f, 0.f, 0.f);
            if (row < M_NODES)
                v = *reinterpret_cast<const float4*>(x + (size_t)row * DCH + kk + j * 4);
            ar[l] = v;
        }
#pragma unroll
        for (int l = 0; l < 4; l++) {
            int t = tid + l * 512, r = t >> 3, j = t & 7;   // 8 float4 per row
            br[l] = *reinterpret_cast<const float4*>(w + (size_t)r * DCH + kk + j * 4);
        }
    };

    auto sts = [&](int buf) {
        __half* a_dst = As + buf * (A_BUF_B / 2);
        __half* b_dst = Bs + buf * (B_BUF_B / 2);
#pragma unroll
        for (int l = 0; l < 2; l++) {
            int t = tid + l * 512, r = t >> 3, j = t & 7;
            float4 v = ar[l];
            __half2 p0 = __floats2half2_rn(v.x, v.y);
            __half2 p1 = __floats2half2_rn(v.z, v.w);
            *reinterpret_cast<uint2*>(&a_dst[r * AS_LD + j * 4]) =
                make_uint2(*reinterpret_cast<uint32_t*>(&p0), *reinterpret_cast<uint32_t*>(&p1));
        }
#pragma unroll
        for (int l = 0; l < 4; l++) {
            int t = tid + l * 512, r = t >> 3, j = t & 7;
            float4 v = br[l];
            __half2 p0 = __floats2half2_rn(v.x, v.y);
            __half2 p1 = __floats2half2_rn(v.z, v.w);
            *reinterpret_cast<uint2*>(&b_dst[r * AS_LD + j * 4]) =
                make_uint2(*reinterpret_cast<uint32_t*>(&p0), *reinterpret_cast<uint32_t*>(&p1));
        }
    };

    auto compute = [&](int buf) {
        const uint32_t as_b = smem_u32(As + buf * (A_BUF_B / 2));
        const uint32_t bs_b = smem_u32(Bs + buf * (B_BUF_B / 2));
#pragma unroll
        for (int ks = 0; ks < 2; ks++) {
            const int k0 = ks * 16;
            uint32_t afrag[2][4];
#pragma unroll
            for (int mt = 0; mt < 2; mt++)
                ldsm_x4(afrag[mt], as_b + 2u * ((mw * 32 + mt * 16 + (lane & 15)) * AS_LD +
                                                (lane >> 4) * 8 + k0));
            uint32_t bfrag[8][2];
#pragma unroll
            for (int nt = 0; nt < 8; nt++)
                ldsm_x2(bfrag[nt], bs_b + 2u * ((nw * 64 + nt * 8 + (lane & 7)) * AS_LD +
                                                ((lane >> 3) & 1) * 8 + k0));
#pragma unroll
            for (int mt = 0; mt < 2; mt++)
#pragma unroll
                for (int nt = 0; nt < 8; nt++)
                    mma_f16(acc[mt][nt], afrag[mt], bfrag[nt]);
        }
    };

    load_g(0);
    sts(0);
    __syncthreads();

#pragma unroll 1
    for (int kt = 0; kt < 8; kt++) {
        const int buf = kt & 1;
        if (kt < 7) load_g(kt + 1);
        compute(buf);
        if (kt < 7) sts(buf ^ 1);
        __syncthreads();
    }

    // epilogue: acc -> g_hh (fp16 packed pairs)
#pragma unroll
    for (int mt = 0; mt < 2; mt++) {
        const int m0 = bm + mw * 32 + mt * 16 + (lane >> 2);
#pragma unroll
        for (int nt = 0; nt < 8; nt++) {
            const int n = nw * 64 + nt * 8 + (lane & 3) * 2;
            __half2 p01 = __floats2half2_rn(acc[mt][nt][0], acc[mt][nt][1]);
            __half2 p23 = __floats2half2_rn(acc[mt][nt][2], acc[mt][nt][3]);
            if (m0 < M_NODES)
                *reinterpret_cast<__half2*>(&g_hh[(size_t)m0 * DCH + n]) = p01;
            if (m0 + 8 < M_NODES)
                *reinterpret_cast<__half2*>(&g_hh[(size_t)(m0 + 8) * DCH + n]) = p23;
        }
    }
}

// ===================== gather: register ping-pong pipeline (R14 proven) ======
#define CE2(arr, a, b) { __half2 _mn = __hmin2(arr[a], arr[b]); \
                         __half2 _mx = __hmax2(arr[a], arr[b]); \
                         arr[a] = _mn; arr[b] = _mx; }

#define OEMS16(arr, o) \
    CE2(arr,o+0,o+1)  CE2(arr,o+2,o+3)   CE2(arr,o+4,o+5)   CE2(arr,o+6,o+7) \
    CE2(arr,o+8,o+9)  CE2(arr,o+10,o+11) CE2(arr,o+12,o+13) CE2(arr,o+14,o+15) \
    CE2(arr,o+0,o+2)  CE2(arr,o+1,o+3)   CE2(arr,o+4,o+6)   CE2(arr,o+5,o+7) \
    CE2(arr,o+8,o+10) CE2(arr,o+9,o+11)  CE2(arr,o+12,o+14) CE2(arr,o+13,o+15) \
    CE2(arr,o+1,o+2)  CE2(arr,o+5,o+6)   CE2(arr,o+9,o+10)  CE2(arr,o+13,o+14) \
    CE2(arr,o+0,o+4)  CE2(arr,o+1,o+5)   CE2(arr,o+2,o+6)   CE2(arr,o+3,o+7) \
    CE2(arr,o+8,o+12) CE2(arr,o+9,o+13)  CE2(arr,o+10,o+14) CE2(arr,o+11,o+15) \
    CE2(arr,o+2,o+4)  CE2(arr,o+3,o+5)   CE2(arr,o+10,o+12) CE2(arr,o+11,o+13) \
    CE2(arr,o+1,o+2)  CE2(arr,o+3,o+4)   CE2(arr,o+5,o+6) \
    CE2(arr,o+9,o+10) CE2(arr,o+11,o+12) CE2(arr,o+13,o+14) \
    CE2(arr,o+0,o+8)  CE2(arr,o+1,o+9)   CE2(arr,o+2,o+10)  CE2(arr,o+3,o+11) \
    CE2(arr,o+4,o+12) CE2(arr,o+5,o+13)  CE2(arr,o+6,o+14)  CE2(arr,o+7,o+15) \
    CE2(arr,o+4,o+8)  CE2(arr,o+5,o+9)   CE2(arr,o+6,o+10)  CE2(arr,o+7,o+11) \
    CE2(arr,o+2,o+4)  CE2(arr,o+3,o+5)   CE2(arr,o+6,o+8) \
    CE2(arr,o+7,o+9)  CE2(arr,o+10,o+12) CE2(arr,o+11,o+13) \
    CE2(arr,o+1,o+2)  CE2(arr,o+3,o+4)   CE2(arr,o+5,o+6)   CE2(arr,o+7,o+8) \
    CE2(arr,o+9,o+10) CE2(arr,o+11,o+12) CE2(arr,o+13,o+14)

#define SELECT32(arr) \
    OEMS16(arr, 0) \
    OEMS16(arr, 16) \
    _Pragma("unroll") \
    for (int i = 0; i < 16; i++) { \
        __half2 _a = arr[i], _b = arr[31 - i]; \
        arr[i]      = __hmin2(_a, _b); \
        arr[31 - i] = __hmax2(_a, _b); \
    } \
    _Pragma("unroll") \
    for (int j = 8; j >= 2; j >>= 1) \
        _Pragma("unroll") \
        for (int i = 0; i < j; i++) \
            arr[i] = __hmax2(arr[i], arr[i + j]); \
    _Pragma("unroll") \
    for (int j = 8; j >= 2; j >>= 1) \
        _Pragma("unroll") \
        for (int i = 0; i < j; i++) \
            arr[16 + i] = __hmin2(arr[16 + i], arr[16 + i + j]);

#define EMIT(arr, nodeidx) { \
    float2 _f0 = __half22float2(arr[0]); \
    float2 _f1 = __half22float2(arr[1]); \
    float2 _f2 = __half22float2(arr[16]); \
    float2 _f3 = __half22float2(arr[17]); \
    float2 _r  = make_float2((_f0.x + _f1.x + _f2.x + _f3.x) * 0.25f, \
                             (_f0.y + _f1.y + _f2.y + _f3.y) * 0.25f); \
    *reinterpret_cast<float2*>(&out[(size_t)(nodeidx) * DCH + 2 * tid]) = _r; }

#define LOADV(arr, j) { \
    _Pragma("unroll") \
    for (int k = 0; k < K_NBR; k++) \
        arr[k] = *reinterpret_cast<const __half2*>(&g_hh[sn[j][k] + 2 * tid]); }

__global__ void __launch_bounds__(128) gather_trim(
    const void* __restrict__ nbrs_raw,
    float* __restrict__ out)
{
    __shared__ int sn[NPN][K_NBR];

    const int tid   = threadIdx.x;
    const int node0 = blockIdx.x * NPN;

    {
        const int* w = reinterpret_cast<const int*>(nbrs_raw);
        unsigned m = __ballot_sync(0xffffffffu, w[2 * (tid & 31) + 1] == 0);
        bool is64 = (m == 0xffffffffu);
#pragma unroll
        for (int i = tid; i < NPN * K_NBR; i += 128) {
            int nl = i >> 5, k = i & 31;
            long long nd = (long long)node0 + nl;
            long long idx = is64
                ? reinterpret_cast<const long long*>(nbrs_raw)[nd * K_NBR + k]
                : (long long)reinterpret_cast<const int*>(nbrs_raw)[nd * K_NBR + k];
            sn[nl][k] = (int)idx * DCH;
        }
    }
    __syncthreads();

    __half2 A[K_NBR], B[K_NBR];

    LOADV(A, 0)
#pragma unroll
    for (int j = 0; j < NPN; j += 2) {
        if (j + 1 < NPN) LOADV(B, j + 1)
        SELECT32(A)
        EMIT(A, node0 + j)
        if (j + 2 < NPN) LOADV(A, j + 2)
        if (j + 1 < NPN) {
            SELECT32(B)
            EMIT(B, node0 + j + 1)
        }
    }
}

// ===================== launch ===============================================
extern "C" void kernel_launch(void* const* d_in, const int* in_sizes, int n_in,
                              void* d_out, int out_size)
{
    const float* x    = nullptr;
    const void*  nbrs = nullptr;
    const float* W    = nullptr;

    for (int i = 0; i < n_in; i++) {
        if      (in_sizes[i] == M_NODES * DCH)   x    = (const float*)d_in[i];
        else if (in_sizes[i] == M_NODES * K_NBR) nbrs = d_in[i];
        else if (in_sizes[i] == DCH * DCH)       W    = (const float*)d_in[i];
    }
    if (!x)    x    = (const float*)d_in[0];
    if (!nbrs) nbrs = d_in[1];
    if (!W)    W    = (const float*)d_in[2];

    cudaFuncSetAttribute(gemm_mma, cudaFuncAttributeMaxDynamicSharedMemorySize, GEMM_SMEM);

    gemm_mma<<<(M_NODES + 127) / 128, 512, GEMM_SMEM>>>(x, W);

    gather_trim<<<M_NODES / NPN, 128>>>(nbrs, (float*)d_out);
}